// round 4
// baseline (speedup 1.0000x reference)
#include <cuda_runtime.h>

namespace {
constexpr int B_     = 2;
constexpr int N_     = 8192;
constexpr int KNN    = 10;
constexpr int KP1    = 11;     // keep self + 10 neighbors
constexpr int SPLIT  = 4;      // candidate-range split per query
constexpr int QPB    = 128;    // queries per block
constexpr int THREADS = QPB * SPLIT;        // 512
constexpr int SUBLEN  = N_ / SPLIT;         // 2048
constexpr int BLOCKS_PER_BATCH = N_ / QPB;  // 64
constexpr int NBLOCKS = B_ * BLOCKS_PER_BATCH; // 128
constexpr int SMEM_BYTES = N_ * 16;         // 131072 bytes (float4 per point)
}

__device__ float g_partials[NBLOCKS];

__global__ __launch_bounds__(THREADS, 1)
void knn_lap_loss_kernel(const float* __restrict__ p1, const float* __restrict__ p2) {
    extern __shared__ unsigned char smem_raw[];
    float4* pts = reinterpret_cast<float4*>(smem_raw);

    const int tid   = threadIdx.x;
    const int b     = blockIdx.x / BLOCKS_PER_BATCH;
    const int qbase = (blockIdx.x % BLOCKS_PER_BATCH) * QPB;
    const float* __restrict__ p1b = p1 + (size_t)b * N_ * 3;
    const float* __restrict__ p2b = p2 + (size_t)b * N_ * 3;

    // ---- Phase 1: stage full batch of point1 into smem as {x,y,z,|c|^2} ----
    for (int i = tid; i < N_; i += THREADS) {
        float x = p1b[i * 3 + 0];
        float y = p1b[i * 3 + 1];
        float z = p1b[i * 3 + 2];
        pts[i] = make_float4(x, y, z, fmaf(x, x, fmaf(y, y, z * z)));
    }
    __syncthreads();

    // ---- Phase 2: brute-force top-11 scan in val-space (|c|^2 - 2 q.c) ----
    const int q   = tid & (QPB - 1);   // warp lanes = consecutive queries -> smem broadcast
    const int sub = tid >> 7;          // 0..3, candidate sub-range
    const int qi  = qbase + q;

    const float4 qp = pts[qi];
    const float m2x = -2.0f * qp.x;
    const float m2y = -2.0f * qp.y;
    const float m2z = -2.0f * qp.z;

    float kd[KP1];
    int   ki[KP1];
#pragma unroll
    for (int t = 0; t < KP1; ++t) { kd[t] = 3.0e38f; ki[t] = -1; }

    const int jbeg = sub * SUBLEN;
#pragma unroll 4
    for (int jo = 0; jo < SUBLEN; ++jo) {
        const int j = jbeg + jo;
        const float4 c = pts[j];
        float v = fmaf(c.x, m2x, c.w);
        v = fmaf(c.y, m2y, v);
        v = fmaf(c.z, m2z, v);
        if (v < kd[KP1 - 1]) {
            float vv = v; int jj = j;
#pragma unroll
            for (int t = KP1 - 1; t >= 0; --t) {
                if (t == 0 || vv >= kd[t - 1]) { kd[t] = vv; ki[t] = jj; break; }
                kd[t] = kd[t - 1]; ki[t] = ki[t - 1];
            }
        }
    }
    __syncthreads();

    // ---- Phase 3: dump per-thread lists to smem (reusing points region) ----
    float* sval = reinterpret_cast<float*>(smem_raw);
    int*   sidx = reinterpret_cast<int*>(smem_raw) + QPB * SPLIT * KP1;
    {
        const int base = (q * SPLIT + sub) * KP1;
#pragma unroll
        for (int t = 0; t < KP1; ++t) { sval[base + t] = kd[t]; sidx[base + t] = ki[t]; }
    }
    __syncthreads();

    // ---- Phase 4: sub==0 threads do a 4-way merge, gather, per-query L1 ----
    float acc = 0.0f;
    if (sub == 0) {
        const float* v0 = sval + (q * SPLIT + 0) * KP1;
        const float* v1 = sval + (q * SPLIT + 1) * KP1;
        const float* v2 = sval + (q * SPLIT + 2) * KP1;
        const float* v3 = sval + (q * SPLIT + 3) * KP1;
        const int*   i0 = sidx + (q * SPLIT + 0) * KP1;
        const int*   i1 = sidx + (q * SPLIT + 1) * KP1;
        const int*   i2 = sidx + (q * SPLIT + 2) * KP1;
        const int*   i3 = sidx + (q * SPLIT + 3) * KP1;

        int c0 = 0, c1 = 0, c2 = 0, c3 = 0;
        int nidx[KP1];
#pragma unroll
        for (int r = 0; r < KP1; ++r) {
            const float h0 = v0[c0], h1 = v1[c1], h2 = v2[c2], h3 = v3[c3];
            const float m = fminf(fminf(h0, h1), fminf(h2, h3));
            int bi;
            if (m == h0)      { bi = i0[c0]; ++c0; }
            else if (m == h1) { bi = i1[c1]; ++c1; }
            else if (m == h2) { bi = i2[c2]; ++c2; }
            else              { bi = i3[c3]; ++c3; }
            nidx[r] = bi;
        }

        // nidx[0] is self (dist 0) -> neighbors are nidx[1..10]
        float sx = 0.0f, sy = 0.0f, sz = 0.0f;
#pragma unroll
        for (int r = 1; r < KP1; ++r) {
            const int bi = nidx[r];
            sx += p1b[bi * 3 + 0] - p2b[bi * 3 + 0];
            sy += p1b[bi * 3 + 1] - p2b[bi * 3 + 1];
            sz += p1b[bi * 3 + 2] - p2b[bi * 3 + 2];
        }
        const float dqx = p1b[qi * 3 + 0] - p2b[qi * 3 + 0];
        const float dqy = p1b[qi * 3 + 1] - p2b[qi * 3 + 1];
        const float dqz = p1b[qi * 3 + 2] - p2b[qi * 3 + 2];
        const float inv_k = 1.0f / (float)KNN;
        acc = fabsf(fmaf(sx, inv_k, -dqx))
            + fabsf(fmaf(sy, inv_k, -dqy))
            + fabsf(fmaf(sz, inv_k, -dqz));
    }

    // ---- Phase 5: deterministic block reduction ----
    float* red = sval + 2 * QPB * SPLIT * KP1;  // disjoint from the list region
    red[tid] = acc;
    __syncthreads();
#pragma unroll
    for (int s = THREADS / 2; s > 0; s >>= 1) {
        if (tid < s) red[tid] += red[tid + s];
        __syncthreads();
    }
    if (tid == 0) g_partials[blockIdx.x] = red[0];
}

__global__ void final_reduce_kernel(float* __restrict__ out) {
    __shared__ float s[NBLOCKS];
    const int t = threadIdx.x;
    s[t] = g_partials[t];
    __syncthreads();
#pragma unroll
    for (int st = NBLOCKS / 2; st > 0; st >>= 1) {
        if (t < st) s[t] += s[t + st];
        __syncthreads();
    }
    if (t == 0) out[0] = s[0] * (1.0f / (float)(B_ * N_ * 3));
}

extern "C" void kernel_launch(void* const* d_in, const int* in_sizes, int n_in,
                              void* d_out, int out_size) {
    const float* p1 = (const float*)d_in[0];
    const float* p2 = (const float*)d_in[1];
    (void)in_sizes; (void)n_in; (void)out_size;

    cudaFuncSetAttribute(knn_lap_loss_kernel,
                         cudaFuncAttributeMaxDynamicSharedMemorySize, SMEM_BYTES);
    knn_lap_loss_kernel<<<NBLOCKS, THREADS, SMEM_BYTES>>>(p1, p2);
    final_reduce_kernel<<<1, NBLOCKS>>>((float*)d_out);
}

// round 6
// speedup vs baseline: 4.3984x; 4.3984x over previous
#include <cuda_runtime.h>

namespace {
constexpr int B_     = 2;
constexpr int N_     = 8192;
constexpr int KNN    = 10;
constexpr int KP1    = 11;     // self + 10 neighbors
constexpr int SPLIT  = 2;      // candidate-range split per query
constexpr int QPB    = 128;    // queries per block
constexpr int THREADS = QPB * SPLIT;        // 256
constexpr int SUBLEN  = N_ / SPLIT;         // 4096
constexpr int GROUP   = 8;                  // candidates per guarded group
constexpr int BLOCKS_PER_BATCH = N_ / QPB;  // 64
constexpr int NBLOCKS = B_ * BLOCKS_PER_BATCH; // 128
constexpr int SMEM_BYTES = N_ * 16;         // 131072 bytes (float4 per point)
}

__device__ float g_partials[NBLOCKS];

// Branchless sorted-insert: 11-level conditional-swap chain.
// Static indexing only -> stays in registers. ~5 ops/level (FSETP+2 FMNMX+2 SEL).
__device__ __forceinline__ void insert11(float v, int j, float (&kd)[KP1], int (&ki)[KP1]) {
#pragma unroll
    for (int t = 0; t < KP1; ++t) {
        const bool  sw = v < kd[t];
        const float nf = sw ? v     : kd[t];
        const float of = sw ? kd[t] : v;
        const int   ni = sw ? j     : ki[t];
        const int   oi = sw ? ki[t] : j;
        kd[t] = nf; ki[t] = ni; v = of; j = oi;
    }
}

__global__ __launch_bounds__(THREADS, 1)
void knn_lap_loss_kernel(const float* __restrict__ p1, const float* __restrict__ p2) {
    extern __shared__ unsigned char smem_raw[];
    float4* pts = reinterpret_cast<float4*>(smem_raw);

    const int tid   = threadIdx.x;
    const int b     = blockIdx.x / BLOCKS_PER_BATCH;
    const int qbase = (blockIdx.x % BLOCKS_PER_BATCH) * QPB;
    const float* __restrict__ p1b = p1 + (size_t)b * N_ * 3;
    const float* __restrict__ p2b = p2 + (size_t)b * N_ * 3;

    // ---- Phase 1: stage full batch of point1 into smem as {x,y,z,|c|^2} ----
    for (int i = tid; i < N_; i += THREADS) {
        float x = p1b[i * 3 + 0];
        float y = p1b[i * 3 + 1];
        float z = p1b[i * 3 + 2];
        pts[i] = make_float4(x, y, z, fmaf(x, x, fmaf(y, y, z * z)));
    }
    __syncthreads();

    // ---- Phase 2: top-11 scan in val-space (|c|^2 - 2 q.c) ----
    // Warp lanes = 32 consecutive queries, same candidate j -> pure smem broadcast.
    const int q   = tid & (QPB - 1);
    const int sub = tid >> 7;          // 0..1
    const int qi  = qbase + q;

    const float4 qp = pts[qi];
    const float m2x = -2.0f * qp.x;
    const float m2y = -2.0f * qp.y;
    const float m2z = -2.0f * qp.z;

    float kd[KP1];
    int   ki[KP1];
#pragma unroll
    for (int t = 0; t < KP1; ++t) { kd[t] = 3.0e38f; ki[t] = 0; }

    const int jbeg = sub * SUBLEN;
    for (int g = 0; g < SUBLEN; g += GROUP) {
        float v[GROUP];
#pragma unroll
        for (int u = 0; u < GROUP; ++u) {
            const float4 c = pts[jbeg + g + u];
            float t0 = fmaf(c.x, m2x, c.w);
            t0 = fmaf(c.y, m2y, t0);
            v[u] = fmaf(c.z, m2z, t0);
        }
        float m = v[0];
#pragma unroll
        for (int u = 1; u < GROUP; ++u) m = fminf(m, v[u]);
        if (m < kd[KP1 - 1]) {
#pragma unroll
            for (int u = 0; u < GROUP; ++u) {
                if (v[u] < kd[KP1 - 1]) insert11(v[u], jbeg + g + u, kd, ki);
            }
        }
    }
    __syncthreads();

    // ---- Phase 3: dump per-thread sorted lists to smem (reuse points region) ----
    float* sval = reinterpret_cast<float*>(smem_raw);
    int*   sidx = reinterpret_cast<int*>(smem_raw) + THREADS * KP1;
    {
        const int base = (q * SPLIT + sub) * KP1;
#pragma unroll
        for (int t = 0; t < KP1; ++t) { sval[base + t] = kd[t]; sidx[base + t] = ki[t]; }
    }
    __syncthreads();

    // ---- Phase 4: sub==0 threads 2-way merge, gather, per-query L1 ----
    float acc = 0.0f;
    if (sub == 0) {
        const float* v0 = sval + (q * SPLIT + 0) * KP1;
        const float* v1 = sval + (q * SPLIT + 1) * KP1;
        const int*   i0 = sidx + (q * SPLIT + 0) * KP1;
        const int*   i1 = sidx + (q * SPLIT + 1) * KP1;

        int c0 = 0, c1 = 0;
        int nidx[KP1];
#pragma unroll
        for (int r = 0; r < KP1; ++r) {
            const float h0 = v0[c0], h1 = v1[c1];
            if (h0 <= h1) { nidx[r] = i0[c0]; ++c0; }
            else          { nidx[r] = i1[c1]; ++c1; }
        }

        // nidx[0] is self (smallest val) -> neighbors are nidx[1..10]
        float sx = 0.0f, sy = 0.0f, sz = 0.0f;
#pragma unroll
        for (int r = 1; r < KP1; ++r) {
            const int bi = nidx[r];
            sx += p1b[bi * 3 + 0] - p2b[bi * 3 + 0];
            sy += p1b[bi * 3 + 1] - p2b[bi * 3 + 1];
            sz += p1b[bi * 3 + 2] - p2b[bi * 3 + 2];
        }
        const float dqx = p1b[qi * 3 + 0] - p2b[qi * 3 + 0];
        const float dqy = p1b[qi * 3 + 1] - p2b[qi * 3 + 1];
        const float dqz = p1b[qi * 3 + 2] - p2b[qi * 3 + 2];
        const float inv_k = 1.0f / (float)KNN;
        acc = fabsf(fmaf(sx, inv_k, -dqx))
            + fabsf(fmaf(sy, inv_k, -dqy))
            + fabsf(fmaf(sz, inv_k, -dqz));
    }

    // ---- Phase 5: deterministic block reduction ----
    float* red = sval + 2 * THREADS * KP1;  // disjoint from list region
    red[tid] = acc;
    __syncthreads();
#pragma unroll
    for (int s = THREADS / 2; s > 0; s >>= 1) {
        if (tid < s) red[tid] += red[tid + s];
        __syncthreads();
    }
    if (tid == 0) g_partials[blockIdx.x] = red[0];
}

__global__ void final_reduce_kernel(float* __restrict__ out) {
    __shared__ float s[NBLOCKS];
    const int t = threadIdx.x;
    s[t] = g_partials[t];
    __syncthreads();
#pragma unroll
    for (int st = NBLOCKS / 2; st > 0; st >>= 1) {
        if (t < st) s[t] += s[t + st];
        __syncthreads();
    }
    if (t == 0) out[0] = s[0] * (1.0f / (float)(B_ * N_ * 3));
}

extern "C" void kernel_launch(void* const* d_in, const int* in_sizes, int n_in,
                              void* d_out, int out_size) {
    const float* p1 = (const float*)d_in[0];
    const float* p2 = (const float*)d_in[1];
    (void)in_sizes; (void)n_in; (void)out_size;

    cudaFuncSetAttribute(knn_lap_loss_kernel,
                         cudaFuncAttributeMaxDynamicSharedMemorySize, SMEM_BYTES);
    knn_lap_loss_kernel<<<NBLOCKS, THREADS, SMEM_BYTES>>>(p1, p2);
    final_reduce_kernel<<<1, NBLOCKS>>>((float*)d_out);
}

// round 7
// speedup vs baseline: 5.9495x; 1.3527x over previous
#include <cuda_runtime.h>

namespace {
constexpr int B_     = 2;
constexpr int N_     = 8192;
constexpr int KNN    = 10;
constexpr int KP1    = 11;     // self + 10 neighbors
constexpr int SPLIT  = 4;      // candidate-range split per query
constexpr int QPB    = 128;    // queries per block
constexpr int THREADS = QPB * SPLIT;        // 512
constexpr int SUBLEN  = N_ / SPLIT;         // 2048
constexpr int GROUP   = 8;                  // candidates per guarded group
constexpr int BLOCKS_PER_BATCH = N_ / QPB;  // 64
constexpr int NBLOCKS = B_ * BLOCKS_PER_BATCH; // 128
constexpr int SMEM_BYTES = N_ * 16;         // 131072 bytes (float4 per point)
constexpr float FINF = 3.0e38f;
}

__device__ float g_partials[NBLOCKS];

// Branchless sorted-insert: 11-level conditional-swap chain (~5 ops/level).
__device__ __forceinline__ void insert11(float v, int j, float (&kd)[KP1], int (&ki)[KP1]) {
#pragma unroll
    for (int t = 0; t < KP1; ++t) {
        const bool  sw = v < kd[t];
        const float nf = sw ? v     : kd[t];
        const float of = sw ? kd[t] : v;
        const int   ni = sw ? j     : ki[t];
        const int   oi = sw ? ki[t] : j;
        kd[t] = nf; ki[t] = ni; v = of; j = oi;
    }
}

__global__ __launch_bounds__(THREADS, 1)
void knn_lap_loss_kernel(const float* __restrict__ p1, const float* __restrict__ p2) {
    extern __shared__ unsigned char smem_raw[];
    float4* pts = reinterpret_cast<float4*>(smem_raw);

    const int tid   = threadIdx.x;
    const int b     = blockIdx.x / BLOCKS_PER_BATCH;
    const int qbase = (blockIdx.x % BLOCKS_PER_BATCH) * QPB;
    const float* __restrict__ p1b = p1 + (size_t)b * N_ * 3;
    const float* __restrict__ p2b = p2 + (size_t)b * N_ * 3;

    // ---- Phase 1: stage full batch of point1 into smem as {x,y,z,|c|^2} ----
    for (int i = tid; i < N_; i += THREADS) {
        float x = p1b[i * 3 + 0];
        float y = p1b[i * 3 + 1];
        float z = p1b[i * 3 + 2];
        pts[i] = make_float4(x, y, z, fmaf(x, x, fmaf(y, y, z * z)));
    }
    __syncthreads();

    // ---- Phase 2: top-11 scan in val-space (|c|^2 - 2 q.c) ----
    // Warp lanes = 32 consecutive queries, same candidate j -> pure smem broadcast.
    const int q   = tid & (QPB - 1);
    const int sub = tid >> 7;          // 0..3
    const int qi  = qbase + q;

    const float4 qp = pts[qi];
    const float m2x = -2.0f * qp.x;
    const float m2y = -2.0f * qp.y;
    const float m2z = -2.0f * qp.z;

    float kd[KP1];
    int   ki[KP1];
#pragma unroll
    for (int t = 0; t < KP1; ++t) { kd[t] = FINF; ki[t] = 0; }

    const int jbeg = sub * SUBLEN;
    for (int g = 0; g < SUBLEN; g += GROUP) {
        const int jg = jbeg + g;
        float v[GROUP];
#pragma unroll
        for (int u = 0; u < GROUP; ++u) {
            const float4 c = pts[jg + u];
            float t0 = fmaf(c.x, m2x, c.w);
            t0 = fmaf(c.y, m2y, t0);
            v[u] = fmaf(c.z, m2z, t0);
        }
        // Iterative min-extraction: ONE insert chain per warp iteration,
        // regardless of how many lanes triggered.
        while (true) {
            float vm = v[0];
            int   am = jg;
#pragma unroll
            for (int u = 1; u < GROUP; ++u) {
                const bool lt = v[u] < vm;
                vm = lt ? v[u] : vm;
                am = lt ? (jg + u) : am;
            }
            const bool pass = vm < kd[KP1 - 1];
            if (!__any_sync(0xffffffffu, pass)) break;
            if (pass) {
                insert11(vm, am, kd, ki);
#pragma unroll
                for (int u = 0; u < GROUP; ++u)
                    v[u] = (am == jg + u) ? FINF : v[u];
            }
        }
    }
    __syncthreads();

    // ---- Phase 3: dump per-thread sorted lists to smem (reuse points region) ----
    float* sval = reinterpret_cast<float*>(smem_raw);
    int*   sidx = reinterpret_cast<int*>(smem_raw) + THREADS * KP1;
    {
        const int base = (q * SPLIT + sub) * KP1;
#pragma unroll
        for (int t = 0; t < KP1; ++t) { sval[base + t] = kd[t]; sidx[base + t] = ki[t]; }
    }
    __syncthreads();

    // ---- Phase 4: sub==0 threads 4-way merge, gather, per-query L1 ----
    float acc = 0.0f;
    if (sub == 0) {
        const float* v0 = sval + (q * SPLIT + 0) * KP1;
        const float* v1 = sval + (q * SPLIT + 1) * KP1;
        const float* v2 = sval + (q * SPLIT + 2) * KP1;
        const float* v3 = sval + (q * SPLIT + 3) * KP1;
        const int*   i0 = sidx + (q * SPLIT + 0) * KP1;
        const int*   i1 = sidx + (q * SPLIT + 1) * KP1;
        const int*   i2 = sidx + (q * SPLIT + 2) * KP1;
        const int*   i3 = sidx + (q * SPLIT + 3) * KP1;

        int c0 = 0, c1 = 0, c2 = 0, c3 = 0;
        int nidx[KP1];
#pragma unroll
        for (int r = 0; r < KP1; ++r) {
            const float h0 = v0[c0], h1 = v1[c1], h2 = v2[c2], h3 = v3[c3];
            const float m = fminf(fminf(h0, h1), fminf(h2, h3));
            int bi;
            if (m == h0)      { bi = i0[c0]; ++c0; }
            else if (m == h1) { bi = i1[c1]; ++c1; }
            else if (m == h2) { bi = i2[c2]; ++c2; }
            else              { bi = i3[c3]; ++c3; }
            nidx[r] = bi;
        }

        // nidx[0] is self (smallest val) -> neighbors are nidx[1..10]
        float sx = 0.0f, sy = 0.0f, sz = 0.0f;
#pragma unroll
        for (int r = 1; r < KP1; ++r) {
            const int bi = nidx[r];
            sx += p1b[bi * 3 + 0] - p2b[bi * 3 + 0];
            sy += p1b[bi * 3 + 1] - p2b[bi * 3 + 1];
            sz += p1b[bi * 3 + 2] - p2b[bi * 3 + 2];
        }
        const float dqx = p1b[qi * 3 + 0] - p2b[qi * 3 + 0];
        const float dqy = p1b[qi * 3 + 1] - p2b[qi * 3 + 1];
        const float dqz = p1b[qi * 3 + 2] - p2b[qi * 3 + 2];
        const float inv_k = 1.0f / (float)KNN;
        acc = fabsf(fmaf(sx, inv_k, -dqx))
            + fabsf(fmaf(sy, inv_k, -dqy))
            + fabsf(fmaf(sz, inv_k, -dqz));
    }

    // ---- Phase 5: deterministic block reduction ----
    float* red = sval + 2 * THREADS * KP1;  // disjoint from list region
    red[tid] = acc;
    __syncthreads();
#pragma unroll
    for (int s = THREADS / 2; s > 0; s >>= 1) {
        if (tid < s) red[tid] += red[tid + s];
        __syncthreads();
    }
    if (tid == 0) g_partials[blockIdx.x] = red[0];
}

__global__ void final_reduce_kernel(float* __restrict__ out) {
    __shared__ float s[NBLOCKS];
    const int t = threadIdx.x;
    s[t] = g_partials[t];
    __syncthreads();
#pragma unroll
    for (int st = NBLOCKS / 2; st > 0; st >>= 1) {
        if (t < st) s[t] += s[t + st];
        __syncthreads();
    }
    if (t == 0) out[0] = s[0] * (1.0f / (float)(B_ * N_ * 3));
}

extern "C" void kernel_launch(void* const* d_in, const int* in_sizes, int n_in,
                              void* d_out, int out_size) {
    const float* p1 = (const float*)d_in[0];
    const float* p2 = (const float*)d_in[1];
    (void)in_sizes; (void)n_in; (void)out_size;

    cudaFuncSetAttribute(knn_lap_loss_kernel,
                         cudaFuncAttributeMaxDynamicSharedMemorySize, SMEM_BYTES);
    knn_lap_loss_kernel<<<NBLOCKS, THREADS, SMEM_BYTES>>>(p1, p2);
    final_reduce_kernel<<<1, NBLOCKS>>>((float*)d_out);
}

// round 9
// speedup vs baseline: 8.5786x; 1.4419x over previous
#include <cuda_runtime.h>

typedef unsigned int u32;
typedef unsigned long long u64;

namespace {
constexpr int B_     = 2;
constexpr int N_     = 8192;
constexpr int KNN    = 10;
constexpr int KP1    = 11;
constexpr int SPLIT  = 4;
constexpr int QPB    = 128;
constexpr int THREADS = QPB * SPLIT;          // 512
constexpr int SUBLEN  = N_ / SPLIT;           // 2048
constexpr int GROUP   = 16;
constexpr int NGROUPS = SUBLEN / GROUP;       // 128
constexpr int WARM    = 6;                    // exact warm-up groups (96 candidates)
constexpr int BLOCKS_PER_BATCH = N_ / QPB;    // 64
constexpr int NBLOCKS = B_ * BLOCKS_PER_BATCH;// 128
constexpr int GTOT    = NBLOCKS * THREADS;    // 65536 threads
constexpr int LOGCAP  = 160;
constexpr u64 STRIDEB = (u64)GTOT * 8ull;     // 512KB between log positions (coalesced)
constexpr int SMEM_BYTES = N_ * 16;           // 128KB point staging
}

__device__ float g_partials[NBLOCKS];
__device__ u64   g_log[(size_t)LOGCAP * GTOT];   // 80MB static scratch (legal)

__device__ __forceinline__ u64 pk2(float a, float b) {
    u64 r; asm("mov.b64 %0, {%1, %2};" : "=l"(r) : "f"(a), "f"(b)); return r;
}
__device__ __forceinline__ u64 fma2(u64 a, u64 b, u64 c) {
    u64 d; asm("fma.rn.f32x2 %0, %1, %2, %3;" : "=l"(d) : "l"(a), "l"(b), "l"(c)); return d;
}
__device__ __forceinline__ u64 add2(u64 a, u64 b) {
    u64 d; asm("add.rn.f32x2 %0, %1, %2;" : "=l"(d) : "l"(a), "l"(b)); return d;
}
__device__ __forceinline__ void unpk(u64 v, u32& lo, u32& hi) {
    asm("mov.b64 {%0, %1}, %2;" : "=r"(lo), "=r"(hi) : "l"(v));
}
__device__ __forceinline__ u32 umn(u32 a, u32 b) { return a < b ? a : b; }  // IMNMX
__device__ __forceinline__ u32 umx(u32 a, u32 b) { return a > b ? a : b; }  // IMNMX

// Branchless packed-key sorted insert: 2 IMNMX per level.
__device__ __forceinline__ void ins11(u32 c, u32 (&kd)[KP1]) {
#pragma unroll
    for (int t = 0; t < KP1; ++t) {
        const u32 lo = umn(c, kd[t]);
        const u32 hi = umx(c, kd[t]);
        kd[t] = lo; c = hi;
    }
}

// Predicated conditional log: if key < thr, store {key, jg} and bump addr.
__device__ __forceinline__ void logcand(u64& addr, u32 key, u32 thr, u32 jgu, u64 stride) {
    asm volatile(
        "{\n\t.reg .pred p;\n\t"
        "setp.lt.u32 p, %1, %2;\n\t"
        "@p st.global.v2.b32 [%0], {%1, %3};\n\t"
        "@p add.u64 %0, %0, %4;\n\t}"
        : "+l"(addr)
        : "r"(key), "r"(thr), "r"(jgu), "l"(stride)
        : "memory");
}

__global__ __launch_bounds__(THREADS, 1)
void knn_lap_loss_kernel(const float* __restrict__ p1, const float* __restrict__ p2) {
    extern __shared__ unsigned char smem_raw[];
    float4* buf = reinterpret_cast<float4*>(smem_raw);

    const int tid   = threadIdx.x;
    const int gtid  = blockIdx.x * THREADS + tid;
    const int b     = blockIdx.x / BLOCKS_PER_BATCH;
    const int qbase = (blockIdx.x % BLOCKS_PER_BATCH) * QPB;
    const float* __restrict__ p1b = p1 + (size_t)b * N_ * 3;
    const float* __restrict__ p2b = p2 + (size_t)b * N_ * 3;

    // ---- Phase 1: stage point1 in pair layout: buf[2p]={x0,x1,y0,y1}, buf[2p+1]={z0,z1,w0,w1}
    for (int p = tid; p < N_ / 2; p += THREADS) {
        const int a = 2 * p, c = 2 * p + 1;
        float xa = p1b[a*3+0], ya = p1b[a*3+1], za = p1b[a*3+2];
        float xb = p1b[c*3+0], yb = p1b[c*3+1], zb = p1b[c*3+2];
        float wa = fmaf(xa, xa, fmaf(ya, ya, za * za));
        float wb = fmaf(xb, xb, fmaf(yb, yb, zb * zb));
        buf[2*p]   = make_float4(xa, xb, ya, yb);
        buf[2*p+1] = make_float4(za, zb, wa, wb);
    }
    __syncthreads();

    // ---- Query constants. vpos = |c-q|^2 + 1 > 0 strictly -> uint order == float order.
    const int q   = tid & (QPB - 1);
    const int sub = tid >> 7;           // 0..3
    const int qi  = qbase + q;
    float qx, qy, qz, qw;
    {
        const int p = qi >> 1, h = qi & 1;
        const float4 A = buf[2*p], Bq = buf[2*p+1];
        qx = h ? A.y  : A.x;  qy = h ? A.w  : A.z;
        qz = h ? Bq.y : Bq.x; qw = h ? Bq.w : Bq.z;
    }
    const u64 m2x2 = pk2(-2.0f*qx, -2.0f*qx);
    const u64 m2y2 = pk2(-2.0f*qy, -2.0f*qy);
    const u64 m2z2 = pk2(-2.0f*qz, -2.0f*qz);
    const float qb = qw + 1.0f;
    const u64 qb2  = pk2(qb, qb);

    u32 kd[KP1];
#pragma unroll
    for (int t = 0; t < KP1; ++t) kd[t] = 0xFFFFFFFFu;

    u64 addr        = (u64)(g_log + gtid);
    const u64 base  = addr;
    const u64 limit = base + (u64)(LOGCAP - GROUP) * STRIDEB;

    const int jbeg = sub * SUBLEN;

    // ---- Phase 2a: WARM exact groups — per-candidate chain insert + record-logging.
    // kd starts at INF so the first 11 candidates ALWAYS log => cnt >= 11 guaranteed.
    for (int g = 0; g < WARM; ++g) {
        const int jg   = jbeg + g * GROUP;
        const int pbeg = jg >> 1;
        u32 key[GROUP];
#pragma unroll
        for (int pp = 0; pp < GROUP / 2; ++pp) {
            const float4 A  = buf[2*(pbeg+pp)];
            const float4 Bc = buf[2*(pbeg+pp)+1];
            u64 acc = add2(pk2(Bc.z, Bc.w), qb2);
            acc = fma2(pk2(A.x, A.y), m2x2, acc);
            acc = fma2(pk2(A.z, A.w), m2y2, acc);
            acc = fma2(pk2(Bc.x, Bc.y), m2z2, acc);
            u32 lo, hi; unpk(acc, lo, hi);
            key[2*pp]   = (lo & 0xFFFFFFF0u) | (u32)(2*pp);
            key[2*pp+1] = (hi & 0xFFFFFFF0u) | (u32)(2*pp+1);
        }
        const bool capok = (addr <= limit);
        const u32 jgu = (u32)jg;
#pragma unroll
        for (int u = 0; u < GROUP; ++u) {
            const u32 thr = capok ? kd[KP1-1] : 0u;   // fresh exact threshold
            logcand(addr, key[u], thr, jgu, STRIDEB);
            ins11(key[u], kd);
        }
    }

    // ---- Phase 2b: main scan — per group: keys, min-tree, predicated log, 1 chain insert.
    for (int g = WARM; g < NGROUPS; ++g) {
        const int jg   = jbeg + g * GROUP;
        const int pbeg = jg >> 1;
        u32 key[GROUP];
#pragma unroll
        for (int pp = 0; pp < GROUP / 2; ++pp) {
            const float4 A  = buf[2*(pbeg+pp)];
            const float4 Bc = buf[2*(pbeg+pp)+1];
            u64 acc = add2(pk2(Bc.z, Bc.w), qb2);
            acc = fma2(pk2(A.x, A.y), m2x2, acc);
            acc = fma2(pk2(A.z, A.w), m2y2, acc);
            acc = fma2(pk2(Bc.x, Bc.y), m2z2, acc);
            u32 lo, hi; unpk(acc, lo, hi);
            key[2*pp]   = (lo & 0xFFFFFFF0u) | (u32)(2*pp);
            key[2*pp+1] = (hi & 0xFFFFFFF0u) | (u32)(2*pp+1);
        }
        // min-tree (15 IMNMX)
        u32 m1;
        {
            u32 a0 = umn(key[0],key[1]),  a1 = umn(key[2],key[3]);
            u32 a2 = umn(key[4],key[5]),  a3 = umn(key[6],key[7]);
            u32 a4 = umn(key[8],key[9]),  a5 = umn(key[10],key[11]);
            u32 a6 = umn(key[12],key[13]),a7 = umn(key[14],key[15]);
            u32 b0 = umn(a0,a1), b1 = umn(a2,a3), b2 = umn(a4,a5), b3 = umn(a6,a7);
            m1 = umn(umn(b0,b1), umn(b2,b3));
        }
        const u32 kd10s = (addr <= limit) ? kd[KP1-1] : 0u;
        const u32 jgu   = (u32)jg;
#pragma unroll
        for (int u = 0; u < GROUP; ++u)
            logcand(addr, key[u], kd10s, jgu, STRIDEB);
        ins11(m1, kd);   // threshold-chain update (group min)
    }

    // ---- Phase 3: exact recovery from this thread's log (branchless packed chain).
    const u32 cnt = (u32)((addr - base) >> 19);   // STRIDEB = 2^19
    u32 rc[KP1];
#pragma unroll
    for (int t = 0; t < KP1; ++t) rc[t] = 0xFFFFFFFFu;
    for (u32 i = 0; i < cnt; ++i) {
        const u64 e = *reinterpret_cast<const u64*>(base + (u64)i * STRIDEB);
        ins11(((u32)e & 0xFFFFFF00u) | i, rc);
    }

    __syncthreads();   // done reading pts; smem will be reused

    // ---- Phase 4: decode indices, dump sorted lists to smem ----
    u32* sval = reinterpret_cast<u32*>(smem_raw);
    u32* sidx = reinterpret_cast<u32*>(smem_raw) + THREADS * KP1;
    {
        const int dbase = (q * SPLIT + sub) * KP1;
#pragma unroll
        for (int r = 0; r < KP1; ++r) {
            const u32 pos = rc[r] & 0xFFu;
            const u64 e = *reinterpret_cast<const u64*>(base + (u64)pos * STRIDEB);
            const u32 j = ((u32)(e >> 32) + ((u32)e & 15u)) & (u32)(N_ - 1);
            sval[dbase + r] = rc[r];
            sidx[dbase + r] = j;
        }
    }
    __syncthreads();

    // ---- Phase 5: sub==0 threads 4-way merge + gather + per-query L1 ----
    float acc = 0.0f;
    if (sub == 0) {
        const u32* v0 = sval + (q * SPLIT + 0) * KP1;
        const u32* v1 = sval + (q * SPLIT + 1) * KP1;
        const u32* v2 = sval + (q * SPLIT + 2) * KP1;
        const u32* v3 = sval + (q * SPLIT + 3) * KP1;
        const u32* i0 = sidx + (q * SPLIT + 0) * KP1;
        const u32* i1 = sidx + (q * SPLIT + 1) * KP1;
        const u32* i2 = sidx + (q * SPLIT + 2) * KP1;
        const u32* i3 = sidx + (q * SPLIT + 3) * KP1;

        int c0 = 0, c1 = 0, c2 = 0, c3 = 0;
        u32 nidx[KP1];
#pragma unroll
        for (int r = 0; r < KP1; ++r) {
            const u32 h0 = v0[c0], h1 = v1[c1], h2 = v2[c2], h3 = v3[c3];
            const u32 m = umn(umn(h0, h1), umn(h2, h3));
            u32 bi;
            if (m == h0)      { bi = i0[c0]; ++c0; }
            else if (m == h1) { bi = i1[c1]; ++c1; }
            else if (m == h2) { bi = i2[c2]; ++c2; }
            else              { bi = i3[c3]; ++c3; }
            nidx[r] = bi;
        }

        // nidx[0] is self -> neighbors are nidx[1..10]
        float sx = 0.0f, sy = 0.0f, sz = 0.0f;
#pragma unroll
        for (int r = 1; r < KP1; ++r) {
            const int bi = (int)nidx[r];
            sx += p1b[bi*3+0] - p2b[bi*3+0];
            sy += p1b[bi*3+1] - p2b[bi*3+1];
            sz += p1b[bi*3+2] - p2b[bi*3+2];
        }
        const float dqx = p1b[qi*3+0] - p2b[qi*3+0];
        const float dqy = p1b[qi*3+1] - p2b[qi*3+1];
        const float dqz = p1b[qi*3+2] - p2b[qi*3+2];
        const float inv_k = 1.0f / (float)KNN;
        acc = fabsf(fmaf(sx, inv_k, -dqx))
            + fabsf(fmaf(sy, inv_k, -dqy))
            + fabsf(fmaf(sz, inv_k, -dqz));
    }

    // ---- Phase 6: deterministic block reduction ----
    float* red = reinterpret_cast<float*>(smem_raw) + 2 * THREADS * KP1;
    red[tid] = acc;
    __syncthreads();
#pragma unroll
    for (int s = THREADS / 2; s > 0; s >>= 1) {
        if (tid < s) red[tid] += red[tid + s];
        __syncthreads();
    }
    if (tid == 0) g_partials[blockIdx.x] = red[0];
}

__global__ void final_reduce_kernel(float* __restrict__ out) {
    __shared__ float s[NBLOCKS];
    const int t = threadIdx.x;
    s[t] = g_partials[t];
    __syncthreads();
#pragma unroll
    for (int st = NBLOCKS / 2; st > 0; st >>= 1) {
        if (t < st) s[t] += s[t + st];
        __syncthreads();
    }
    if (t == 0) out[0] = s[0] * (1.0f / (float)(B_ * N_ * 3));
}

extern "C" void kernel_launch(void* const* d_in, const int* in_sizes, int n_in,
                              void* d_out, int out_size) {
    const float* p1 = (const float*)d_in[0];
    const float* p2 = (const float*)d_in[1];
    (void)in_sizes; (void)n_in; (void)out_size;

    cudaFuncSetAttribute(knn_lap_loss_kernel,
                         cudaFuncAttributeMaxDynamicSharedMemorySize, SMEM_BYTES);
    knn_lap_loss_kernel<<<NBLOCKS, THREADS, SMEM_BYTES>>>(p1, p2);
    final_reduce_kernel<<<1, NBLOCKS>>>((float*)d_out);
}